// round 1
// baseline (speedup 1.0000x reference)
#include <cuda_runtime.h>
#include <cuda_bf16.h>
#include <math.h>

#define NSEQ 2048
#define HID  2048
#define NH   32
#define DK   128
#define PROJ 4096
#define QSCALE 0.08838834764831843f   // 128^-0.5

// ---------------- scratch (device globals; no allocation allowed) ----------------
__device__ float g_Qp[NSEQ * PROJ];
__device__ float g_Kp[NSEQ * PROJ];
__device__ float g_Vp[NSEQ * PROJ];
__device__ float g_Qc[NSEQ * PROJ];
__device__ float g_Kc[NSEQ * PROJ];
__device__ float g_Vc[NSEQ * PROJ];
__device__ float g_F[NSEQ * PROJ];     // f, overwritten in-place with exp(g)
__device__ float g_GATE[NSEQ * PROJ];  // gate pre-activation
__device__ float g_CORE[NSEQ * PROJ];  // scan output, then gated-rms output in place
__device__ float g_FA[NSEQ * DK];
__device__ float g_GA[NSEQ * DK];
__device__ float g_BRAW[NSEQ * NH];

// ---------------- generic C = A[M,K] * B[N,K]^T (both row-major) ----------------
// 128x128 block tile, 16 K-tile, 8x8 per-thread register tile, 256 threads,
// register prefetch of next global tile.
__global__ void __launch_bounds__(256) gemm_nt_kernel(
    const float* __restrict__ A, const float* __restrict__ B, float* __restrict__ C,
    int M, int Nn, int Kd) {
  __shared__ float As[16][132];
  __shared__ float Bs[16][132];
  const int tid  = threadIdx.x;
  const int bm   = blockIdx.y * 128;
  const int bn   = blockIdx.x * 128;
  const int tx   = tid & 15;
  const int ty   = tid >> 4;
  const int row0 = ty * 8;
  const int col0 = tx * 8;
  const int lr   = tid >> 1;        // 0..127
  const int lc   = (tid & 1) * 8;   // 0 or 8

  const float* Aptr = A + (size_t)(bm + lr) * Kd + lc;
  const bool bvalid = (bn + lr) < Nn;
  const float* Bptr = B + (size_t)(bn + lr) * Kd + lc;

  float4 pa0, pa1, pb0, pb1;
  pa0 = *reinterpret_cast<const float4*>(Aptr);
  pa1 = *reinterpret_cast<const float4*>(Aptr + 4);
  if (bvalid) {
    pb0 = *reinterpret_cast<const float4*>(Bptr);
    pb1 = *reinterpret_cast<const float4*>(Bptr + 4);
  } else {
    pb0 = make_float4(0.f, 0.f, 0.f, 0.f);
    pb1 = pb0;
  }

  float acc[8][8];
#pragma unroll
  for (int i = 0; i < 8; i++)
#pragma unroll
    for (int j = 0; j < 8; j++) acc[i][j] = 0.f;

  for (int k0 = 0; k0 < Kd; k0 += 16) {
    // store prefetched tiles (transposed: [k][m])
    As[lc + 0][lr] = pa0.x; As[lc + 1][lr] = pa0.y;
    As[lc + 2][lr] = pa0.z; As[lc + 3][lr] = pa0.w;
    As[lc + 4][lr] = pa1.x; As[lc + 5][lr] = pa1.y;
    As[lc + 6][lr] = pa1.z; As[lc + 7][lr] = pa1.w;
    Bs[lc + 0][lr] = pb0.x; Bs[lc + 1][lr] = pb0.y;
    Bs[lc + 2][lr] = pb0.z; Bs[lc + 3][lr] = pb0.w;
    Bs[lc + 4][lr] = pb1.x; Bs[lc + 5][lr] = pb1.y;
    Bs[lc + 6][lr] = pb1.z; Bs[lc + 7][lr] = pb1.w;
    __syncthreads();

    const int kn = k0 + 16;
    if (kn < Kd) {
      pa0 = *reinterpret_cast<const float4*>(Aptr + kn);
      pa1 = *reinterpret_cast<const float4*>(Aptr + kn + 4);
      if (bvalid) {
        pb0 = *reinterpret_cast<const float4*>(Bptr + kn);
        pb1 = *reinterpret_cast<const float4*>(Bptr + kn + 4);
      }
    }

#pragma unroll
    for (int kk = 0; kk < 16; kk++) {
      float a[8], b[8];
      float4 t0 = *reinterpret_cast<const float4*>(&As[kk][row0]);
      float4 t1 = *reinterpret_cast<const float4*>(&As[kk][row0 + 4]);
      float4 u0 = *reinterpret_cast<const float4*>(&Bs[kk][col0]);
      float4 u1 = *reinterpret_cast<const float4*>(&Bs[kk][col0 + 4]);
      a[0] = t0.x; a[1] = t0.y; a[2] = t0.z; a[3] = t0.w;
      a[4] = t1.x; a[5] = t1.y; a[6] = t1.z; a[7] = t1.w;
      b[0] = u0.x; b[1] = u0.y; b[2] = u0.z; b[3] = u0.w;
      b[4] = u1.x; b[5] = u1.y; b[6] = u1.z; b[7] = u1.w;
#pragma unroll
      for (int i = 0; i < 8; i++)
#pragma unroll
        for (int j = 0; j < 8; j++) acc[i][j] = fmaf(a[i], b[j], acc[i][j]);
    }
    __syncthreads();
  }

#pragma unroll
  for (int i = 0; i < 8; i++) {
    float* Cr = C + (size_t)(bm + row0 + i) * Nn;
#pragma unroll
    for (int j = 0; j < 8; j++) {
      int cc = bn + col0 + j;
      if (cc < Nn) Cr[cc] = acc[i][j];
    }
  }
}

// -------- depthwise causal conv(K=4) + SiLU, optional per-(n,h) L2 norm --------
__global__ void __launch_bounds__(128) conv_silu_kernel(
    const float* __restrict__ X, const float* __restrict__ W,
    float* __restrict__ Y, int do_norm, float scale) {
  const int h = blockIdx.x;
  const int n = blockIdx.y;
  const int tid = threadIdx.x;
  const int c = h * DK + tid;
  float y = 0.f;
#pragma unroll
  for (int i = 0; i < 4; i++) {
    int nn = n - 3 + i;
    if (nn >= 0) y = fmaf(X[(size_t)nn * PROJ + c], W[c * 4 + i], y);
  }
  y = y / (1.f + expf(-y));  // SiLU
  __shared__ float red[4];
  if (do_norm) {
    float ss = y * y;
#pragma unroll
    for (int o = 16; o > 0; o >>= 1) ss += __shfl_xor_sync(0xffffffffu, ss, o);
    if ((tid & 31) == 0) red[tid >> 5] = ss;
    __syncthreads();
    float tot = red[0] + red[1] + red[2] + red[3];
    y *= rsqrtf(tot + 1e-6f) * scale;
  }
  Y[(size_t)n * PROJ + c] = y;
}

// -------- exp(g) = exp(-exp(A_log[h]) * softplus(f + dt_bias)), in place --------
__global__ void __launch_bounds__(256) gate_decay_kernel(
    float* __restrict__ F, const float* __restrict__ dt_bias,
    const float* __restrict__ A_log) {
  const int idx = blockIdx.x * 256 + threadIdx.x;
  const int c = idx & (PROJ - 1);
  const int h = c >> 7;
  float x = F[idx] + dt_bias[c];
  float sp = (x > 20.f) ? x : log1pf(expf(x));
  F[idx] = expf(-expf(A_log[h]) * sp);
}

// ---------------- sequential delta-rule scan ----------------
// grid: 32 heads x 4 v-slices = 128 blocks, 256 threads.
// thread (vloc = tid>>3 in [0,32), kc = tid&7 in [0,8)) owns S[kc*16 + j][v], j<16.
// Inputs double-buffered in shared with register prefetch; k/q/eg stored in a
// transposed-swizzled layout so inner-loop LDS are pure broadcasts.
__global__ void __launch_bounds__(256, 1) scan_kernel(
    const float* __restrict__ Q, const float* __restrict__ K,
    const float* __restrict__ V, const float* __restrict__ EG,
    const float* __restrict__ BRAW, float* __restrict__ O) {
  const int h = blockIdx.x >> 2;
  const int vbase = (blockIdx.x & 3) << 5;
  const int tid = threadIdx.x;
  const int vloc = tid >> 3;
  const int kc = tid & 7;

  __shared__ float k_sh[2][128], q_sh[2][128], e_sh[2][128];
  __shared__ float v_sh[2][32];
  __shared__ float b_sh[2];

  float S[16];
#pragma unroll
  for (int j = 0; j < 16; j++) S[j] = 0.f;

  const size_t hb = (size_t)h * DK;
  float pk = 0.f, pe = 0.f, pq = 0.f, pv = 0.f, pb = 0.f;

  // prefetch t = 0
  if (tid < 128) {
    pk = K[hb + tid];
    pe = EG[hb + tid];
  } else {
    int u = tid - 128;
    pq = Q[hb + u];
    if (u < 32) pv = V[hb + vbase + u];
    if (u == 127) pb = BRAW[h];
  }

  for (int t = 0; t < NSEQ; t++) {
    const int buf = t & 1;
    if (tid < 128) {
      int sw = ((tid & 15) << 3) | (tid >> 4);
      k_sh[buf][sw] = pk;
      e_sh[buf][sw] = pe;
    } else {
      int u = tid - 128;
      q_sh[buf][((u & 15) << 3) | (u >> 4)] = pq;
      if (u < 32) v_sh[buf][u] = pv;
      if (u == 127) b_sh[buf] = 1.f / (1.f + expf(-pb));
    }
    __syncthreads();

    if (t + 1 < NSEQ) {
      size_t off = (size_t)(t + 1) * PROJ + hb;
      if (tid < 128) {
        pk = K[off + tid];
        pe = EG[off + tid];
      } else {
        int u = tid - 128;
        pq = Q[off + u];
        if (u < 32) pv = V[off + vbase + u];
        if (u == 127) pb = BRAW[(size_t)(t + 1) * NH + h];
      }
    }

    float kreg[16];
    float kv0 = 0.f, kv1 = 0.f;
#pragma unroll
    for (int j = 0; j < 16; j++) {
      float e = e_sh[buf][(j << 3) | kc];
      float kk = k_sh[buf][(j << 3) | kc];
      kreg[j] = kk;
      float s = S[j] * e;
      S[j] = s;
      if (j & 1) kv1 = fmaf(kk, s, kv1); else kv0 = fmaf(kk, s, kv0);
    }
    float kv = kv0 + kv1;
    kv += __shfl_xor_sync(0xffffffffu, kv, 1);
    kv += __shfl_xor_sync(0xffffffffu, kv, 2);
    kv += __shfl_xor_sync(0xffffffffu, kv, 4);

    const float delta = (v_sh[buf][vloc] - kv) * b_sh[buf];

    float o0 = 0.f, o1 = 0.f;
#pragma unroll
    for (int j = 0; j < 16; j++) {
      float q = q_sh[buf][(j << 3) | kc];
      float s = fmaf(kreg[j], delta, S[j]);
      S[j] = s;
      if (j & 1) o1 = fmaf(q, s, o1); else o0 = fmaf(q, s, o0);
    }
    float o = o0 + o1;
    o += __shfl_xor_sync(0xffffffffu, o, 1);
    o += __shfl_xor_sync(0xffffffffu, o, 2);
    o += __shfl_xor_sync(0xffffffffu, o, 4);
    if (kc == 0) O[(size_t)t * PROJ + hb + vbase + vloc] = o;
    __syncthreads();
  }
}

// -------- gated RMSNorm: core = rms(core) * onorm_w * sigmoid(gate), in place --------
__global__ void __launch_bounds__(128) out_gate_kernel(
    float* __restrict__ CORE, const float* __restrict__ GATE,
    const float* __restrict__ onorm_w) {
  const int h = blockIdx.x;
  const int n = blockIdx.y;
  const int tid = threadIdx.x;
  const size_t idx = (size_t)n * PROJ + h * DK + tid;
  float cv = CORE[idx];
  float ss = cv * cv;
#pragma unroll
  for (int o = 16; o > 0; o >>= 1) ss += __shfl_xor_sync(0xffffffffu, ss, o);
  __shared__ float red[4];
  if ((tid & 31) == 0) red[tid >> 5] = ss;
  __syncthreads();
  float tot = red[0] + red[1] + red[2] + red[3];
  float r = rsqrtf(tot * (1.f / 128.f) + 1e-5f);
  float gt = GATE[idx];
  CORE[idx] = cv * r * onorm_w[tid] / (1.f + expf(-gt));
}

// ---------------- launch ----------------
extern "C" void kernel_launch(void* const* d_in, const int* in_sizes, int n_in,
                              void* d_out, int out_size) {
  const float* hs      = (const float*)d_in[0];
  const float* Wq      = (const float*)d_in[1];
  const float* Wk      = (const float*)d_in[2];
  const float* Wv      = (const float*)d_in[3];
  const float* conv_q  = (const float*)d_in[4];
  const float* conv_k  = (const float*)d_in[5];
  const float* conv_v  = (const float*)d_in[6];
  const float* Wfa     = (const float*)d_in[7];
  const float* Wfb     = (const float*)d_in[8];
  const float* dt_bias = (const float*)d_in[9];
  const float* Wb      = (const float*)d_in[10];
  const float* A_log   = (const float*)d_in[11];
  const float* Wga     = (const float*)d_in[12];
  const float* Wgb     = (const float*)d_in[13];
  const float* onorm_w = (const float*)d_in[14];
  const float* Wo      = (const float*)d_in[15];
  float* out = (float*)d_out;

  float *Qp, *Kp, *Vp, *Qc, *Kc, *Vc, *F, *GATE, *CORE, *FA, *GA, *BRAW;
  cudaGetSymbolAddress((void**)&Qp,   g_Qp);
  cudaGetSymbolAddress((void**)&Kp,   g_Kp);
  cudaGetSymbolAddress((void**)&Vp,   g_Vp);
  cudaGetSymbolAddress((void**)&Qc,   g_Qc);
  cudaGetSymbolAddress((void**)&Kc,   g_Kc);
  cudaGetSymbolAddress((void**)&Vc,   g_Vc);
  cudaGetSymbolAddress((void**)&F,    g_F);
  cudaGetSymbolAddress((void**)&GATE, g_GATE);
  cudaGetSymbolAddress((void**)&CORE, g_CORE);
  cudaGetSymbolAddress((void**)&FA,   g_FA);
  cudaGetSymbolAddress((void**)&GA,   g_GA);
  cudaGetSymbolAddress((void**)&BRAW, g_BRAW);

  const dim3 blk256(256);
  const dim3 gProj(PROJ / 128, NSEQ / 128);   // (32,16)
  const dim3 gLow(1, NSEQ / 128);             // N<=128
  const dim3 gOut(HID / 128, NSEQ / 128);     // (16,16)

  // projections
  gemm_nt_kernel<<<gProj, blk256>>>(hs, Wq, Qp, NSEQ, PROJ, HID);
  gemm_nt_kernel<<<gProj, blk256>>>(hs, Wk, Kp, NSEQ, PROJ, HID);
  gemm_nt_kernel<<<gProj, blk256>>>(hs, Wv, Vp, NSEQ, PROJ, HID);
  gemm_nt_kernel<<<gLow,  blk256>>>(hs, Wfa, FA, NSEQ, DK, HID);
  gemm_nt_kernel<<<gLow,  blk256>>>(hs, Wga, GA, NSEQ, DK, HID);
  gemm_nt_kernel<<<gLow,  blk256>>>(hs, Wb, BRAW, NSEQ, NH, HID);
  gemm_nt_kernel<<<gProj, blk256>>>(FA, Wfb, F,    NSEQ, PROJ, DK);
  gemm_nt_kernel<<<gProj, blk256>>>(GA, Wgb, GATE, NSEQ, PROJ, DK);

  // conv + silu (+ l2 norm for q,k)
  dim3 gConv(NH, NSEQ);
  conv_silu_kernel<<<gConv, 128>>>(Qp, conv_q, Qc, 1, QSCALE);
  conv_silu_kernel<<<gConv, 128>>>(Kp, conv_k, Kc, 1, 1.0f);
  conv_silu_kernel<<<gConv, 128>>>(Vp, conv_v, Vc, 0, 1.0f);

  // exp(g) in place over F
  gate_decay_kernel<<<(NSEQ * PROJ) / 256, 256>>>(F, dt_bias, A_log);

  // recurrent scan
  scan_kernel<<<NH * 4, 256>>>(Qc, Kc, Vc, F, BRAW, CORE);

  // gated rmsnorm (in place over CORE)
  out_gate_kernel<<<gConv, 128>>>(CORE, GATE, onorm_w);

  // output projection
  gemm_nt_kernel<<<gOut, blk256>>>(CORE, Wo, out, NSEQ, HID, PROJ);
}